// round 15
// baseline (speedup 1.0000x reference)
#include <cuda_runtime.h>
#include <cuda_fp16.h>
#include <cstdint>
#include <cstddef>

// Problem constants
#define BATCH   16384
#define DIM     512
#define HID     128     // H
#define HID2    256     // 2H
#define NG      18
#define DAGG    640     // D + H

// ---------------------------------------------------------------------------
// Scratch (device globals; allocation-free rule)
// ---------------------------------------------------------------------------
__device__ float  g_w[(size_t)BATCH * NG];                   // masked attention weights
__device__ __half g_Xh[(size_t)BATCH * DIM];                 // X cast to fp16
__device__ __half g_W1h[(size_t)NG * HID2 * DIM];            // weights n-major [g][N][K] fp16
__device__ __half g_W2h[(size_t)NG * HID * HID2];
__device__ __half g_W3h[(size_t)NG * HID * HID];
__device__ __half g_Waggh[(size_t)DIM * DAGG];               // [N=512][K=640]
__device__ __half g_Wah[(size_t)32 * DIM];                   // Wa padded n-major [32][512]
__device__ __half g_H1h[(size_t)NG * BATCH * HID2];          // H1 compacted, fp16
__device__ __half g_H3h[(size_t)NG * BATCH * HID];           // H3 compacted, fp16
__device__ __half g_Rh[(size_t)BATCH * HID];                 // refinements fp16
__device__ int    g_counts[32];                              // members per genre
__device__ int    g_idx[(size_t)NG * BATCH];                 // genre -> member rows
__device__ int    g_pos[(size_t)BATCH * NG];                 // (b,g) -> slot

// ---------------------------------------------------------------------------
// Helpers
// ---------------------------------------------------------------------------
__device__ __forceinline__ uint32_t smem_u32(const void* p) {
    uint32_t a;
    asm("{ .reg .u64 t; cvta.to.shared.u64 t, %1; cvt.u32.u64 %0, t; }" : "=r"(a) : "l"(p));
    return a;
}
__device__ __forceinline__ void cp_async16(uint32_t dst, const void* src) {
    asm volatile("cp.async.cg.shared.global [%0], [%1], 16;" :: "r"(dst), "l"(src) : "memory");
}
#define CP_COMMIT() asm volatile("cp.async.commit_group;" ::: "memory")
#define CP_WAIT(n)  asm volatile("cp.async.wait_group %0;" :: "n"(n) : "memory")

__device__ __forceinline__ void ldsm_x4(uint32_t addr, uint32_t* r) {
    asm volatile("ldmatrix.sync.aligned.m8n8.x4.shared.b16 {%0,%1,%2,%3}, [%4];"
        : "=r"(r[0]), "=r"(r[1]), "=r"(r[2]), "=r"(r[3]) : "r"(addr));
}

// fp16 MMA m16n8k16, fp32 accumulate
__device__ __forceinline__ void mma16(float* d, const uint32_t* a, const uint32_t* b) {
    asm volatile(
        "mma.sync.aligned.m16n8k16.row.col.f32.f16.f16.f32 "
        "{%0,%1,%2,%3}, {%4,%5,%6,%7}, {%8,%9}, {%0,%1,%2,%3};"
        : "+f"(d[0]), "+f"(d[1]), "+f"(d[2]), "+f"(d[3])
        : "r"(a[0]), "r"(a[1]), "r"(a[2]), "r"(a[3]), "r"(b[0]), "r"(b[1]));
}

// ---------------------------------------------------------------------------
// Prep (fused): weight transpose+cast tiles, X cast, counts zeroing, Wa pad.
// ---------------------------------------------------------------------------
#define PREP_TILES 3488
#define PREP_CAST  512
#define PREP_WAH   16
#define PREP_TOTAL (PREP_TILES + PREP_CAST + PREP_WAH)

__global__ __launch_bounds__(256)
void prep_kernel(const float* __restrict__ W1, const float* __restrict__ W2,
                 const float* __restrict__ W3, const float* __restrict__ Wagg,
                 const float* __restrict__ X, const float* __restrict__ Wa,
                 __half* __restrict__ W1h, __half* __restrict__ W2h,
                 __half* __restrict__ W3h, __half* __restrict__ Waggh,
                 __half* __restrict__ Xh, __half* __restrict__ Wah,
                 int* __restrict__ counts) {
    int bz = blockIdx.x;
    int tid = threadIdx.x;

    if (bz >= PREP_TILES + PREP_CAST) {
        int kb = (bz - PREP_TILES - PREP_CAST) * 32;
        for (int e = tid; e < 32 * 32; e += 256) {
            int k = kb + (e >> 5), n = e & 31;
            float v = (n < NG) ? Wa[(size_t)k * NG + n] : 0.f;
            Wah[(size_t)n * DIM + k] = __float2half_rn(v);
        }
        return;
    }
    if (bz >= PREP_TILES) {
        int local = bz - PREP_TILES;
        if (local == 0 && tid < 32) counts[tid] = 0;
        int n4 = BATCH * DIM / 4;
        for (int i = local * 256 + tid; i < n4; i += PREP_CAST * 256) {
            float4 v = ((const float4*)X)[i];
            __half2 h0 = __floats2half2_rn(v.x, v.y);
            __half2 h1 = __floats2half2_rn(v.z, v.w);
            uint2 p;
            p.x = *(uint32_t*)&h0;
            p.y = *(uint32_t*)&h1;
            ((uint2*)Xh)[i] = p;
        }
        return;
    }

    __shared__ float t[32][33];
    const float* in;
    __half* out;
    int K, N, g, tt;
    if (bz < 2304)      { g = bz / 128;          tt = bz % 128; in = W1;   out = W1h;   K = DIM;  N = HID2; }
    else if (bz < 2880) { bz -= 2304; g = bz / 32; tt = bz % 32; in = W2;   out = W2h;   K = HID2; N = HID;  }
    else if (bz < 3168) { bz -= 2880; g = bz / 16; tt = bz % 16; in = W3;   out = W3h;   K = HID;  N = HID;  }
    else                { bz -= 3168; g = 0;       tt = bz;      in = Wagg; out = Waggh; K = DAGG; N = DIM;  }
    in  += (size_t)g * K * N;
    out += (size_t)g * K * N;
    int ntn = N / 32;
    int k0 = (tt / ntn) * 32;
    int n0 = (tt % ntn) * 32;
    int tx = tid & 31, ty = tid >> 5;
    #pragma unroll
    for (int i = 0; i < 4; i++) {
        int r = ty + i * 8;
        t[r][tx] = in[(size_t)(k0 + r) * N + n0 + tx];
    }
    __syncthreads();
    #pragma unroll
    for (int i = 0; i < 4; i++) {
        int r = ty + i * 8;
        out[(size_t)(n0 + r) * K + k0 + tx] = __float2half_rn(t[tx][r]);
    }
}

// ---------------------------------------------------------------------------
// Membership compaction, coalesced
// ---------------------------------------------------------------------------
__global__ __launch_bounds__(256)
void compact_kernel(const float* __restrict__ genre, int* __restrict__ counts,
                    int* __restrict__ idxArr, int* __restrict__ pos) {
    __shared__ float gt[256][19];
    __shared__ int   ps[256][19];
    int b0 = blockIdx.x * 256;
    int tid = threadIdx.x;
    for (int i = tid; i < 256 * NG; i += 256) {
        gt[i / NG][i % NG] = genre[(size_t)b0 * NG + i];
    }
    __syncthreads();
    int warp = tid >> 5, lane = tid & 31;
    for (int g = warp; g < NG; g += 8) {
        unsigned masks[8];
        int total = 0;
        #pragma unroll
        for (int s = 0; s < 8; s++) {
            float v = gt[s * 32 + lane][g];
            masks[s] = __ballot_sync(0xffffffffu, v > 0.f);
            total += __popc(masks[s]);
        }
        int base = 0;
        if (lane == 0) base = atomicAdd(&counts[g], total);
        base = __shfl_sync(0xffffffffu, base, 0);
        int run = 0;
        #pragma unroll
        for (int s = 0; s < 8; s++) {
            unsigned m = masks[s];
            if (m & (1u << lane)) {
                int slot = base + run + __popc(m & ((1u << lane) - 1u));
                idxArr[(size_t)g * BATCH + slot] = b0 + s * 32 + lane;
                ps[s * 32 + lane][g] = slot;
            }
            run += __popc(m);
        }
    }
    __syncthreads();
    for (int i = tid; i < 256 * NG; i += 256) {
        pos[(size_t)b0 * NG + i] = ps[i / NG][i % NG];
    }
}

// ---------------------------------------------------------------------------
// Tensor-core attention (unchanged from R14)
// ---------------------------------------------------------------------------
#define AT_LDH 72
#define AT_ASZ (128 * AT_LDH)
#define AT_BSZ (32 * AT_LDH)
#define AT_CT_OFF (2 * AT_ASZ + 2 * AT_BSZ)
#define AT_SMEM (AT_CT_OFF * 2 + 128 * 33 * 4)

__global__ __launch_bounds__(256)
void attn_tc_kernel(const __half* __restrict__ Xh, const __half* __restrict__ Wah,
                    const float* __restrict__ ba, const float* __restrict__ genre,
                    float* __restrict__ w) {
    extern __shared__ __half smh[];
    __half* As = smh;
    __half* Bs = smh + 2 * AT_ASZ;
    float*  Ct = (float*)(smh + AT_CT_OFF);
    uint32_t as_u = smem_u32(As);
    uint32_t bs_u = smem_u32(Bs);

    int m0 = blockIdx.x * 128;
    int tid = threadIdx.x;
    int lane = tid & 31, warp = tid >> 5;

    float acc[4][4];
    #pragma unroll
    for (int i = 0; i < 4; i++)
        #pragma unroll
        for (int r = 0; r < 4; r++) acc[i][r] = 0.f;

    int lr = tid >> 3, lc = (tid & 7) * 8;

    int lane8 = lane & 7;
    uint32_t a_off = (uint32_t)(((16 * warp + lane8 + ((lane >> 3) & 1) * 8) * AT_LDH
                                 + (lane >> 4) * 8) * 2);
    uint32_t b_off[2];
    #pragma unroll
    for (int p = 0; p < 2; p++)
        b_off[p] = (uint32_t)(((p * 16 + lane8 + (lane >> 4) * 8) * AT_LDH
                               + ((lane >> 3) & 1) * 8) * 2);

    auto stage = [&](int bsel, int k0) {
        uint32_t abase = as_u + (uint32_t)(bsel * AT_ASZ) * 2;
        #pragma unroll
        for (int rr = 0; rr < 4; rr++) {
            int r = lr + rr * 32;
            cp_async16(abase + (uint32_t)(r * AT_LDH + lc) * 2,
                       Xh + (size_t)(m0 + r) * DIM + k0 + lc);
        }
        uint32_t bbase = bs_u + (uint32_t)(bsel * AT_BSZ) * 2;
        int n = tid >> 3;
        cp_async16(bbase + (uint32_t)(n * AT_LDH + lc) * 2,
                   Wah + (size_t)n * DIM + k0 + lc);
    };

    stage(0, 0);
    CP_COMMIT();
    for (int c = 0; c < 8; c++) {
        int cur = c & 1;
        if (c < 7) {
            stage(cur ^ 1, (c + 1) * 64);
            CP_COMMIT();
            CP_WAIT(1);
        } else {
            CP_WAIT(0);
        }
        __syncthreads();
        uint32_t ab = as_u + (uint32_t)(cur * AT_ASZ) * 2;
        uint32_t bb = bs_u + (uint32_t)(cur * AT_BSZ) * 2;
        #pragma unroll
        for (int kk = 0; kk < 4; kk++) {
            uint32_t kb = (uint32_t)(kk * 16 * 2);
            uint32_t af[4], bf[2][4];
            ldsm_x4(ab + a_off + kb, af);
            ldsm_x4(bb + b_off[0] + kb, bf[0]);
            ldsm_x4(bb + b_off[1] + kb, bf[1]);
            mma16(acc[0], af, &bf[0][0]);
            mma16(acc[1], af, &bf[0][2]);
            mma16(acc[2], af, &bf[1][0]);
            mma16(acc[3], af, &bf[1][2]);
        }
        __syncthreads();
    }

    #pragma unroll
    for (int wn = 0; wn < 4; wn++) {
        int c0 = wn * 8 + 2 * (lane & 3);
        int r0 = 16 * warp + (lane >> 2);
        Ct[r0 * 33 + c0]       = acc[wn][0];
        Ct[r0 * 33 + c0 + 1]   = acc[wn][1];
        Ct[(r0 + 8) * 33 + c0]     = acc[wn][2];
        Ct[(r0 + 8) * 33 + c0 + 1] = acc[wn][3];
    }
    __syncthreads();

    if (tid < 128) {
        int b = m0 + tid;
        float l[NG];
        float mx = -1e30f;
        #pragma unroll
        for (int g = 0; g < NG; g++) {
            l[g] = Ct[tid * 33 + g] + ba[g];
            mx = fmaxf(mx, l[g]);
        }
        float s = 0.f;
        #pragma unroll
        for (int g = 0; g < NG; g++) {
            l[g] = expf(l[g] - mx);
            s += l[g];
        }
        float inv = 1.f / s;
        #pragma unroll
        for (int g = 0; g < NG; g++) {
            float gv = genre[(size_t)b * NG + g];
            w[(size_t)b * NG + g] = (gv > 0.f) ? l[g] * inv * gv : 0.f;
        }
    }
}

// ---------------------------------------------------------------------------
// GEMM1 high-occupancy: H1c = relu(gather(Xh) @ W1^T + b1), fp16 out.
// BM=128, BN=64, BK=32, warp tile 32x32 (acc 32 regs), 4-stage cp.async,
// __launch_bounds__(256, 3) -> <=84 regs -> 3 CTAs/SM (24 warps).
// ---------------------------------------------------------------------------
#define G1_BM  128
#define G1_BN  64
#define G1_BK  32
#define G1_LD  40                       // 32 + 8 pad halves; 80B stride, ldsm-safe
#define G1_ASZ (128 * G1_LD)
#define G1_BSZ (64 * G1_LD)
#define G1_STG (G1_ASZ + G1_BSZ)        // halves per stage
#define G1_NST 4
#define G1_SMEM (G1_NST * G1_STG * 2)   // 61440 bytes

__global__ __launch_bounds__(256, 3)
void gemm1_hiocc_kernel(const __half* __restrict__ Xh, const __half* __restrict__ W1,
                        const float* __restrict__ b1, __half* __restrict__ H1,
                        const int* __restrict__ idxArr, const int* __restrict__ counts) {
    int g = blockIdx.z;
    int m0 = blockIdx.x * G1_BM;
    int cnt = counts[g];
    if (m0 >= cnt) return;
    W1 += (size_t)g * HID2 * DIM;
    b1 += (size_t)g * HID2;
    const int* gidx = idxArr + (size_t)g * BATCH;
    __half* Hout = H1 + (size_t)g * BATCH * HID2;

    extern __shared__ __half smh[];
    uint32_t s_u = smem_u32(smh);

    int tid = threadIdx.x;
    int n0 = blockIdx.y * G1_BN;
    int lane = tid & 31, warp = tid >> 5;
    int wm_base = (warp >> 1) * 32;     // 4 m-groups
    int wn_base = (warp & 1) * 32;      // 2 n-groups

    float acc[2][4][4];
    #pragma unroll
    for (int i = 0; i < 2; i++)
        #pragma unroll
        for (int j = 0; j < 4; j++)
            #pragma unroll
            for (int r = 0; r < 4; r++) acc[i][j][r] = 0.f;

    // loaders: 64 rows/pass, 4 threads/row x 8 halves (16B)
    int lr = tid >> 2, lc = (tid & 3) * 8;

    const __half* arow_ptr[2];
    #pragma unroll
    for (int rr = 0; rr < 2; rr++) {
        int grow = m0 + lr + rr * 64;
        int cl = (grow < cnt) ? grow : (cnt - 1);
        arow_ptr[rr] = Xh + (size_t)gidx[cl] * DIM;
    }

    int lane8 = lane & 7;
    uint32_t a_off[2];
    #pragma unroll
    for (int m = 0; m < 2; m++) {
        int row = wm_base + m * 16 + lane8 + ((lane >> 3) & 1) * 8;
        int kof = (lane >> 4) * 8;
        a_off[m] = (uint32_t)((row * G1_LD + kof) * 2);
    }
    uint32_t b_off[2];
    #pragma unroll
    for (int p = 0; p < 2; p++) {
        int row = wn_base + p * 16 + lane8 + (lane >> 4) * 8;
        int kof = ((lane >> 3) & 1) * 8;
        b_off[p] = (uint32_t)((G1_ASZ + row * G1_LD + kof) * 2);
    }

    auto stage = [&](int bsel, int k0) {
        uint32_t base = s_u + (uint32_t)(bsel * G1_STG) * 2;
        #pragma unroll
        for (int rr = 0; rr < 2; rr++) {
            int r = lr + rr * 64;
            cp_async16(base + (uint32_t)(r * G1_LD + lc) * 2,
                       arow_ptr[rr] + k0 + lc);
        }
        cp_async16(base + (uint32_t)((G1_ASZ + lr * G1_LD + lc)) * 2,
                   W1 + (size_t)(n0 + lr) * DIM + k0 + lc);
    };

    const int nchunks = DIM / G1_BK;    // 16
    stage(0, 0);           CP_COMMIT();
    stage(1, G1_BK);       CP_COMMIT();
    stage(2, 2 * G1_BK);   CP_COMMIT();

    for (int c = 0; c < nchunks; c++) {
        CP_WAIT(2);
        __syncthreads();
        if (c + 3 < nchunks) stage((c + 3) & 3, (c + 3) * G1_BK);
        CP_COMMIT();   // unconditional (empty group in tail keeps wait(2) exact)

        uint32_t sb = s_u + (uint32_t)((c & 3) * G1_STG) * 2;
        #pragma unroll
        for (int kk = 0; kk < 2; kk++) {
            uint32_t kb = (uint32_t)(kk * 16 * 2);
            uint32_t af[2][4], bf[2][4];
            ldsm_x4(sb + a_off[0] + kb, af[0]);
            ldsm_x4(sb + a_off[1] + kb, af[1]);
            ldsm_x4(sb + b_off[0] + kb, bf[0]);
            ldsm_x4(sb + b_off[1] + kb, bf[1]);
            #pragma unroll
            for (int m = 0; m < 2; m++)
                #pragma unroll
                for (int p = 0; p < 2; p++) {
                    mma16(acc[m][2 * p],     af[m], &bf[p][0]);
                    mma16(acc[m][2 * p + 1], af[m], &bf[p][2]);
                }
        }
    }

    #pragma unroll
    for (int m = 0; m < 2; m++) {
        int r0 = m0 + wm_base + m * 16 + (lane >> 2);
        #pragma unroll
        for (int j = 0; j < 4; j++) {
            int c0 = n0 + wn_base + j * 8 + 2 * (lane & 3);
            float b0 = b1[c0], b1v = b1[c0 + 1];
            float v0 = fmaxf(acc[m][j][0] + b0, 0.f);
            float v1 = fmaxf(acc[m][j][1] + b1v, 0.f);
            float v2 = fmaxf(acc[m][j][2] + b0, 0.f);
            float v3 = fmaxf(acc[m][j][3] + b1v, 0.f);
            *(__half2*)(Hout + (size_t)r0 * HID2 + c0)       = __floats2half2_rn(v0, v1);
            *(__half2*)(Hout + (size_t)(r0 + 8) * HID2 + c0) = __floats2half2_rn(v2, v3);
        }
    }
}

// ---------------------------------------------------------------------------
// Shared GEMM geometry (proven path, used by agg GEMM)
// ---------------------------------------------------------------------------
#define BM  128
#define BN  128
#define BKH 64
#define LDH 72
#define TSZ (128 * LDH)
#define NSTAGE 3
#define GEMM_SMEM_BYTES (2 * NSTAGE * TSZ * 2)

template<int ACT, int OUTH, int MODE>
__global__ __launch_bounds__(256, 2)
void gemm_fp16_kernel(const __half* __restrict__ A, const __half* __restrict__ Rp,
                      const __half* __restrict__ W, const float* __restrict__ bias,
                      void* __restrict__ Cv,
                      int N, int K, int lda,
                      long long sA, long long sW, long long sB, long long sC,
                      const int* __restrict__ idxArr, const int* __restrict__ counts) {
    int g = blockIdx.z;
    int m0 = blockIdx.x * BM;
    int cnt = 0;
    if (MODE == 1) {
        cnt = counts[g];
        if (m0 >= cnt) return;
    }
    A    += (size_t)g * sA;
    W    += (size_t)g * sW;
    bias += (size_t)g * sB;
    const int* gidx = idxArr + (size_t)g * BATCH;

    extern __shared__ __half smh[];
    __half* As = smh;
    __half* Bs = smh + NSTAGE * TSZ;
    uint32_t as_u = smem_u32(As);
    uint32_t bs_u = smem_u32(Bs);

    int tid  = threadIdx.x;
    int n0   = blockIdx.y * BN;
    int lane = tid & 31, warp = tid >> 5;
    int wm_base = (warp >> 1) * 32;
    int wn_base = (warp & 1) * 64;

    float acc[2][8][4];
    #pragma unroll
    for (int i = 0; i < 2; i++)
        #pragma unroll
        for (int j = 0; j < 8; j++)
            #pragma unroll
            for (int r = 0; r < 4; r++) acc[i][j][r] = 0.f;

    int lr = tid >> 3, lc = (tid & 7) * 8;

    const __half* arow_ptr[4];
    #pragma unroll
    for (int rr = 0; rr < 4; rr++) {
        int grow = m0 + lr + rr * 32;
        if (MODE == 1) {
            int cl = (grow < cnt) ? grow : (cnt - 1);
            arow_ptr[rr] = A + (size_t)gidx[cl] * lda;
        } else {
            arow_ptr[rr] = A + (size_t)grow * lda;
        }
    }

    int lane8 = lane & 7;
    uint32_t a_off[2];
    #pragma unroll
    for (int wm = 0; wm < 2; wm++) {
        int row = wm_base + wm * 16 + lane8 + ((lane >> 3) & 1) * 8;
        int kof = (lane >> 4) * 8;
        a_off[wm] = (uint32_t)((row * LDH + kof) * 2);
    }
    uint32_t b_off[4];
    #pragma unroll
    for (int wnp = 0; wnp < 4; wnp++) {
        int row = wn_base + wnp * 16 + lane8 + (lane >> 4) * 8;
        int kof = ((lane >> 3) & 1) * 8;
        b_off[wnp] = (uint32_t)((row * LDH + kof) * 2);
    }

    int nchunks = K / BKH;

    auto stage = [&](int bsel, int k0) {
        uint32_t abase = as_u + (uint32_t)(bsel * TSZ) * 2;
        #pragma unroll
        for (int rr = 0; rr < 4; rr++) {
            int r = lr + rr * 32;
            int gcol = k0 + lc;
            const __half* src;
            if (MODE == 3) {
                int grow = m0 + r;
                src = (gcol < DIM) ? (A + (size_t)grow * DIM + gcol)
                                   : (Rp + (size_t)grow * HID + (gcol - DIM));
            } else {
                src = arow_ptr[rr] + gcol;
            }
            cp_async16(abase + (uint32_t)(r * LDH + lc) * 2, src);
        }
        uint32_t bbase = bs_u + (uint32_t)(bsel * TSZ) * 2;
        #pragma unroll
        for (int rr = 0; rr < 4; rr++) {
            int n = lr + rr * 32;
            cp_async16(bbase + (uint32_t)(n * LDH + lc) * 2,
                       W + (size_t)(n0 + n) * K + k0 + lc);
        }
    };

    stage(0, 0);
    CP_COMMIT();
    if (nchunks > 1) {
        stage(1, BKH);
        CP_COMMIT();
    }

    for (int c = 0; c < nchunks; c++) {
        if (c + 1 < nchunks) { CP_WAIT(1); } else { CP_WAIT(0); }
        __syncthreads();
        if (c + 2 < nchunks) {
            stage((c + 2) % NSTAGE, (c + 2) * BKH);
            CP_COMMIT();
        }
        int cur = c % NSTAGE;
        uint32_t ab = as_u + (uint32_t)(cur * TSZ) * 2;
        uint32_t bb = bs_u + (uint32_t)(cur * TSZ) * 2;

        #pragma unroll
        for (int kk = 0; kk < 4; kk++) {
            uint32_t kb = (uint32_t)(kk * 16 * 2);
            uint32_t af[2][4], bf[4][4];
            ldsm_x4(ab + a_off[0] + kb, af[0]);
            ldsm_x4(ab + a_off[1] + kb, af[1]);
            #pragma unroll
            for (int wnp = 0; wnp < 4; wnp++)
                ldsm_x4(bb + b_off[wnp] + kb, bf[wnp]);
            #pragma unroll
            for (int wm = 0; wm < 2; wm++)
                #pragma unroll
                for (int wnp = 0; wnp < 4; wnp++) {
                    mma16(acc[wm][2 * wnp],     af[wm], &bf[wnp][0]);
                    mma16(acc[wm][2 * wnp + 1], af[wm], &bf[wnp][2]);
                }
        }
    }

    #pragma unroll
    for (int wm = 0; wm < 2; wm++) {
        int r0 = m0 + wm_base + wm * 16 + (lane >> 2);
        #pragma unroll
        for (int wn = 0; wn < 8; wn++) {
            int c0 = n0 + wn_base + wn * 8 + 2 * (lane & 3);
            float b0 = bias[c0], b1v = bias[c0 + 1];
            float v0 = acc[wm][wn][0] + b0;
            float v1 = acc[wm][wn][1] + b1v;
            float v2 = acc[wm][wn][2] + b0;
            float v3 = acc[wm][wn][3] + b1v;
            if (ACT) {
                v0 = fmaxf(v0, 0.f); v1 = fmaxf(v1, 0.f);
                v2 = fmaxf(v2, 0.f); v3 = fmaxf(v3, 0.f);
            }
            if (OUTH) {
                __half* C = (__half*)Cv + (size_t)g * sC;
                __half2 p0 = __floats2half2_rn(v0, v1);
                __half2 p1 = __floats2half2_rn(v2, v3);
                *(__half2*)(C + (size_t)r0 * N + c0)       = p0;
                *(__half2*)(C + (size_t)(r0 + 8) * N + c0) = p1;
            } else {
                float* C = (float*)Cv + (size_t)g * sC;
                *(float2*)(C + (size_t)r0 * N + c0)       = make_float2(v0, v1);
                *(float2*)(C + (size_t)(r0 + 8) * N + c0) = make_float2(v2, v3);
            }
        }
    }
}

// ---------------------------------------------------------------------------
// Fused GEMM2+GEMM3 (unchanged from R14)
// ---------------------------------------------------------------------------
#define LDH2 136
#define H2TSZ (128 * LDH2)
#define G23_STAGE_BYTES (4 * TSZ * 2)
#define GEMM23_SMEM_BYTES (G23_STAGE_BYTES + H2TSZ * 2)

__global__ __launch_bounds__(256, 2)
void gemm23_fused_kernel(const __half* __restrict__ H1, const __half* __restrict__ W2,
                         const __half* __restrict__ W3,
                         const float* __restrict__ b2, const float* __restrict__ b3,
                         __half* __restrict__ H3,
                         const int* __restrict__ counts) {
    int g = blockIdx.z;
    int m0 = blockIdx.x * BM;
    if (m0 >= counts[g]) return;
    H1 += (size_t)g * BATCH * HID2;
    W2 += (size_t)g * HID * HID2;
    W3 += (size_t)g * HID * HID;
    b2 += (size_t)g * HID;
    b3 += (size_t)g * HID;
    H3 += (size_t)g * BATCH * HID;

    extern __shared__ __half smh[];
    __half* As  = smh;
    __half* Bs  = smh + 2 * TSZ;
    __half* H2s = smh + 4 * TSZ;
    uint32_t as_u  = smem_u32(As);
    uint32_t bs_u  = smem_u32(Bs);
    uint32_t h2_u  = smem_u32(H2s);

    int tid  = threadIdx.x;
    int lane = tid & 31, warp = tid >> 5;
    int wm_base = (warp >> 1) * 32;
    int wn_base = (warp & 1) * 64;

    float acc[2][8][4];
    #pragma unroll
    for (int i = 0; i < 2; i++)
        #pragma unroll
        for (int j = 0; j < 8; j++)
            #pragma unroll
            for (int r = 0; r < 4; r++) acc[i][j][r] = 0.f;

    int lr = tid >> 3, lc = (tid & 7) * 8;

    int lane8 = lane & 7;
    uint32_t a_off[2], a2_off[2];
    #pragma unroll
    for (int wm = 0; wm < 2; wm++) {
        int row = wm_base + wm * 16 + lane8 + ((lane >> 3) & 1) * 8;
        int kof = (lane >> 4) * 8;
        a_off[wm]  = (uint32_t)((row * LDH  + kof) * 2);
        a2_off[wm] = (uint32_t)((row * LDH2 + kof) * 2);
    }
    uint32_t b_off[4];
    #pragma unroll
    for (int wnp = 0; wnp < 4; wnp++) {
        int row = wn_base + wnp * 16 + lane8 + (lane >> 4) * 8;
        int kof = ((lane >> 3) & 1) * 8;
        b_off[wnp] = (uint32_t)((row * LDH + kof) * 2);
    }

    auto stage1 = [&](int bsel, int k0) {
        uint32_t abase = as_u + (uint32_t)(bsel * TSZ) * 2;
        #pragma unroll
        for (int rr = 0; rr < 4; rr++) {
            int r = lr + rr * 32;
            cp_async16(abase + (uint32_t)(r * LDH + lc) * 2,
                       H1 + (size_t)(m0 + r) * HID2 + k0 + lc);
        }
        uint32_t bbase = bs_u + (uint32_t)(bsel * TSZ) * 2;
        #pragma unroll
        for (int rr = 0; rr < 4; rr++) {
            int n = lr + rr * 32;
            cp_async16(bbase + (uint32_t)(n * LDH + lc) * 2,
                       W2 + (size_t)n * HID2 + k0 + lc);
        }
    };
    auto stage_w3 = [&](int bsel, int k0) {
        uint32_t bbase = bs_u + (uint32_t)(bsel * TSZ) * 2;
        #pragma unroll
        for (int rr = 0; rr < 4; rr++) {
            int n = lr + rr * 32;
            cp_async16(bbase + (uint32_t)(n * LDH + lc) * 2,
                       W3 + (size_t)n * HID + k0 + lc);
        }
    };

    auto mma_block = [&](uint32_t ab, uint32_t bb, const uint32_t* aoff) {
        #pragma unroll
        for (int kk = 0; kk < 4; kk++) {
            uint32_t kb = (uint32_t)(kk * 16 * 2);
            uint32_t af[2][4], bf[4][4];
            ldsm_x4(ab + aoff[0] + kb, af[0]);
            ldsm_x4(ab + aoff[1] + kb, af[1]);
            #pragma unroll
            for (int wnp = 0; wnp < 4; wnp++)
                ldsm_x4(bb + b_off[wnp] + kb, bf[wnp]);
            #pragma unroll
            for (int wm = 0; wm < 2; wm++)
                #pragma unroll
                for (int wnp = 0; wnp < 4; wnp++) {
                    mma16(acc[wm][2 * wnp],     af[wm], &bf[wnp][0]);
                    mma16(acc[wm][2 * wnp + 1], af[wm], &bf[wnp][2]);
                }
        }
    };

    stage1(0, 0);
    CP_COMMIT();
    for (int c = 0; c < 4; c++) {
        int cur = c & 1;
        if (c < 3) {
            stage1(cur ^ 1, (c + 1) * BKH);
            CP_COMMIT();
            CP_WAIT(1);
        } else {
            stage_w3(0, 0);
            CP_COMMIT();
            CP_WAIT(1);
        }
        __syncthreads();
        mma_block(as_u + (uint32_t)(cur * TSZ) * 2, bs_u + (uint32_t)(cur * TSZ) * 2, a_off);
        __syncthreads();
    }

    #pragma unroll
    for (int wm = 0; wm < 2; wm++) {
        int r0 = wm_base + wm * 16 + (lane >> 2);
        #pragma unroll
        for (int wn = 0; wn < 8; wn++) {
            int c0 = wn_base + wn * 8 + 2 * (lane & 3);
            float b0 = b2[c0], b1v = b2[c0 + 1];
            float v0 = fmaxf(acc[wm][wn][0] + b0, 0.f);
            float v1 = fmaxf(acc[wm][wn][1] + b1v, 0.f);
            float v2 = fmaxf(acc[wm][wn][2] + b0, 0.f);
            float v3 = fmaxf(acc[wm][wn][3] + b1v, 0.f);
            *(__half2*)(H2s + r0 * LDH2 + c0)       = __floats2half2_rn(v0, v1);
            *(__half2*)(H2s + (r0 + 8) * LDH2 + c0) = __floats2half2_rn(v2, v3);
            acc[wm][wn][0] = 0.f; acc[wm][wn][1] = 0.f;
            acc[wm][wn][2] = 0.f; acc[wm][wn][3] = 0.f;
        }
    }
    stage_w3(1, BKH);
    CP_COMMIT();
    CP_WAIT(0);
    __syncthreads();

    #pragma unroll
    for (int c2 = 0; c2 < 2; c2++) {
        uint32_t ab = h2_u + (uint32_t)(c2 * BKH) * 2;
        uint32_t bb = bs_u + (uint32_t)(c2 * TSZ) * 2;
        mma_block(ab, bb, a2_off);
    }

    #pragma unroll
    for (int wm = 0; wm < 2; wm++) {
        int r0 = wm_base + wm * 16 + (lane >> 2);
        #pragma unroll
        for (int wn = 0; wn < 8; wn++) {
            int c0 = wn_base + wn * 8 + 2 * (lane & 3);
            float b0 = b3[c0], b1v = b3[c0 + 1];
            float v0 = acc[wm][wn][0] + b0;
            float v1 = acc[wm][wn][1] + b1v;
            float v2 = acc[wm][wn][2] + b0;
            float v3 = acc[wm][wn][3] + b1v;
            *(__half2*)(H3 + (size_t)(m0 + r0) * HID + c0)     = __floats2half2_rn(v0, v1);
            *(__half2*)(H3 + (size_t)(m0 + r0 + 8) * HID + c0) = __floats2half2_rn(v2, v3);
        }
    }
}

// ---------------------------------------------------------------------------
// Weighted reduce (compacted, fp16 H3)
// ---------------------------------------------------------------------------
__global__ __launch_bounds__(256)
void reduce_kernel(const __half* __restrict__ H3, const float* __restrict__ w,
                   const int* __restrict__ pos, __half* __restrict__ Rh) {
    int idx = blockIdx.x * blockDim.x + threadIdx.x;
    int b = idx >> 5;
    int off = idx & 31;
    float r0 = 0.f, r1 = 0.f, r2 = 0.f, r3 = 0.f;
    const uint2* H = (const uint2*)H3;
    #pragma unroll
    for (int g = 0; g < NG; g++) {
        float wv = w[(size_t)b * NG + g];
        if (wv != 0.f) {
            int slot = pos[(size_t)b * NG + g];
            uint2 h = H[((size_t)g * BATCH + slot) * 32 + off];
            float2 f0 = __half22float2(*(__half2*)&h.x);
            float2 f1 = __half22float2(*(__half2*)&h.y);
            r0 += wv * f0.x; r1 += wv * f0.y;
            r2 += wv * f1.x; r3 += wv * f1.y;
        }
    }
    __half2 p0 = __floats2half2_rn(r0, r1);
    __half2 p1 = __floats2half2_rn(r2, r3);
    uint2 p;
    p.x = *(uint32_t*)&p0;
    p.y = *(uint32_t*)&p1;
    ((uint2*)Rh)[idx] = p;
}

// ---------------------------------------------------------------------------
// Launch
// ---------------------------------------------------------------------------
extern "C" void kernel_launch(void* const* d_in, const int* in_sizes, int n_in,
                              void* d_out, int out_size) {
    (void)in_sizes; (void)n_in; (void)out_size;
    const float* X     = (const float*)d_in[0];
    const float* genre = (const float*)d_in[1];
    const float* W1    = (const float*)d_in[2];
    const float* b1    = (const float*)d_in[3];
    const float* W2    = (const float*)d_in[4];
    const float* b2    = (const float*)d_in[5];
    const float* W3    = (const float*)d_in[6];
    const float* b3    = (const float*)d_in[7];
    const float* Wa    = (const float*)d_in[8];
    const float* ba    = (const float*)d_in[9];
    const float* Wagg  = (const float*)d_in[10];
    const float* bagg  = (const float*)d_in[11];
    float* out = (float*)d_out;

    float *w;
    __half *Xh, *W1h, *W2h, *W3h, *Waggh, *Wah, *H1h, *H3h, *Rh;
    int *counts, *idxArr, *pos;
    cudaGetSymbolAddress((void**)&w,      g_w);
    cudaGetSymbolAddress((void**)&Xh,     g_Xh);
    cudaGetSymbolAddress((void**)&W1h,    g_W1h);
    cudaGetSymbolAddress((void**)&W2h,    g_W2h);
    cudaGetSymbolAddress((void**)&W3h,    g_W3h);
    cudaGetSymbolAddress((void**)&Waggh,  g_Waggh);
    cudaGetSymbolAddress((void**)&Wah,    g_Wah);
    cudaGetSymbolAddress((void**)&H1h,    g_H1h);
    cudaGetSymbolAddress((void**)&H3h,    g_H3h);
    cudaGetSymbolAddress((void**)&Rh,     g_Rh);
    cudaGetSymbolAddress((void**)&counts, g_counts);
    cudaGetSymbolAddress((void**)&idxArr, g_idx);
    cudaGetSymbolAddress((void**)&pos,    g_pos);

    cudaFuncSetAttribute(gemm1_hiocc_kernel,
                         cudaFuncAttributeMaxDynamicSharedMemorySize, G1_SMEM);
    cudaFuncSetAttribute(gemm_fp16_kernel<1, 0, 3>,
                         cudaFuncAttributeMaxDynamicSharedMemorySize, GEMM_SMEM_BYTES);
    cudaFuncSetAttribute(gemm23_fused_kernel,
                         cudaFuncAttributeMaxDynamicSharedMemorySize, GEMM23_SMEM_BYTES);
    cudaFuncSetAttribute(attn_tc_kernel,
                         cudaFuncAttributeMaxDynamicSharedMemorySize, AT_SMEM);

    // 0) prep + compaction
    prep_kernel<<<PREP_TOTAL, 256>>>(W1, W2, W3, Wagg, X, Wa,
                                     W1h, W2h, W3h, Waggh, Xh, Wah, counts);
    compact_kernel<<<BATCH / 256, 256>>>(genre, counts, idxArr, pos);

    // 1) attention weights via tensor cores
    attn_tc_kernel<<<BATCH / 128, 256, AT_SMEM>>>(Xh, Wah, ba, genre, w);

    // 2) H1c = relu(gather(Xh) @ W1[g]^T + b1[g]) -> fp16 (high-occupancy)
    gemm1_hiocc_kernel<<<dim3(BATCH / G1_BM, HID2 / G1_BN, NG), 256, G1_SMEM>>>(
        Xh, W1h, b1, H1h, idxArr, counts);

    // 3+4) fused: H3c = (relu(H1c @ W2^T + b2)) @ W3^T + b3 -> fp16
    gemm23_fused_kernel<<<dim3(BATCH / BM, 1, NG), 256, GEMM23_SMEM_BYTES>>>(
        H1h, W2h, W3h, b2, b3, H3h, counts);

    // 5) Rh = fp16( sum_g w .* H3c[pos] )
    reduce_kernel<<<(BATCH * 32) / 256, 256>>>(H3h, w, pos, Rh);

    // 6) out = relu([Xh, Rh] @ Wagg^T + bagg) -> fp32
    gemm_fp16_kernel<1, 0, 3><<<dim3(BATCH / BM, DIM / BN, 1), 256, GEMM_SMEM_BYTES>>>(
        Xh, Rh, Waggh, bagg, out,
        DIM, DAGG, DAGG,
        0LL, 0LL, 0LL, 0LL,
        idxArr, counts);
}

// round 16
// speedup vs baseline: 1.0852x; 1.0852x over previous
#include <cuda_runtime.h>
#include <cuda_fp16.h>
#include <cstdint>
#include <cstddef>

// Problem constants
#define BATCH   16384
#define DIM     512
#define HID     128     // H
#define HID2    256     // 2H
#define NG      18
#define DAGG    640     // D + H

// ---------------------------------------------------------------------------
// Scratch (device globals; allocation-free rule)
// ---------------------------------------------------------------------------
__device__ float  g_w[(size_t)BATCH * NG];                   // masked attention weights
__device__ __half g_Xh[(size_t)BATCH * DIM];                 // X cast to fp16
__device__ __half g_W1h[(size_t)NG * HID2 * DIM];            // weights n-major [g][N][K] fp16
__device__ __half g_W2h[(size_t)NG * HID * HID2];
__device__ __half g_W3h[(size_t)NG * HID * HID];
__device__ __half g_Waggh[(size_t)DIM * DAGG];               // [N=512][K=640]
__device__ __half g_Wah[(size_t)32 * DIM];                   // Wa padded n-major [32][512]
__device__ __half g_H1h[(size_t)NG * BATCH * HID2];          // H1 compacted, fp16
__device__ __half g_H3h[(size_t)NG * BATCH * HID];           // H3 compacted, fp16
__device__ __half g_Rh[(size_t)BATCH * HID];                 // refinements fp16
__device__ int    g_counts[32];                              // members per genre
__device__ int    g_idx[(size_t)NG * BATCH];                 // genre -> member rows
__device__ int    g_pos[(size_t)BATCH * NG];                 // (b,g) -> slot

// ---------------------------------------------------------------------------
// Helpers
// ---------------------------------------------------------------------------
__device__ __forceinline__ uint32_t smem_u32(const void* p) {
    uint32_t a;
    asm("{ .reg .u64 t; cvta.to.shared.u64 t, %1; cvt.u32.u64 %0, t; }" : "=r"(a) : "l"(p));
    return a;
}
__device__ __forceinline__ void cp_async16(uint32_t dst, const void* src) {
    asm volatile("cp.async.cg.shared.global [%0], [%1], 16;" :: "r"(dst), "l"(src) : "memory");
}
#define CP_COMMIT() asm volatile("cp.async.commit_group;" ::: "memory")
#define CP_WAIT(n)  asm volatile("cp.async.wait_group %0;" :: "n"(n) : "memory")

__device__ __forceinline__ void ldsm_x4(uint32_t addr, uint32_t* r) {
    asm volatile("ldmatrix.sync.aligned.m8n8.x4.shared.b16 {%0,%1,%2,%3}, [%4];"
        : "=r"(r[0]), "=r"(r[1]), "=r"(r[2]), "=r"(r[3]) : "r"(addr));
}

// fp16 MMA m16n8k16, fp32 accumulate
__device__ __forceinline__ void mma16(float* d, const uint32_t* a, const uint32_t* b) {
    asm volatile(
        "mma.sync.aligned.m16n8k16.row.col.f32.f16.f16.f32 "
        "{%0,%1,%2,%3}, {%4,%5,%6,%7}, {%8,%9}, {%0,%1,%2,%3};"
        : "+f"(d[0]), "+f"(d[1]), "+f"(d[2]), "+f"(d[3])
        : "r"(a[0]), "r"(a[1]), "r"(a[2]), "r"(a[3]), "r"(b[0]), "r"(b[1]));
}

// ---------------------------------------------------------------------------
// Prep + compact (fused; counts zeroed by a prior memset node):
//   blocks [0, 3488): 32x32 transpose+cast tiles over W1|W2|W3|Wagg
//   blocks [3488, 4000): grid-stride fp32->fp16 cast of X
//   blocks [4000, 4016): Wa [512][18] -> Wah [32][512] n-major fp16, padded
//   blocks [4016, 4080): membership compaction (256 rows per block)
// ---------------------------------------------------------------------------
#define PREP_TILES 3488
#define PREP_CAST  512
#define PREP_WAH   16
#define PREP_TOTAL (PREP_TILES + PREP_CAST + PREP_WAH)
#define PREP_GRID  (PREP_TOTAL + BATCH / 256)

__global__ __launch_bounds__(256)
void prep_compact_kernel(const float* __restrict__ W1, const float* __restrict__ W2,
                         const float* __restrict__ W3, const float* __restrict__ Wagg,
                         const float* __restrict__ X, const float* __restrict__ Wa,
                         const float* __restrict__ genre,
                         __half* __restrict__ W1h, __half* __restrict__ W2h,
                         __half* __restrict__ W3h, __half* __restrict__ Waggh,
                         __half* __restrict__ Xh, __half* __restrict__ Wah,
                         int* __restrict__ counts, int* __restrict__ idxArr,
                         int* __restrict__ pos) {
    __shared__ float t[32][33];
    __shared__ float gt[256][19];
    __shared__ int   ps[256][19];

    int bz = blockIdx.x;
    int tid = threadIdx.x;

    if (bz >= PREP_TOTAL) {
        // ---- compaction region ----
        int b0 = (bz - PREP_TOTAL) * 256;
        for (int i = tid; i < 256 * NG; i += 256) {
            gt[i / NG][i % NG] = genre[(size_t)b0 * NG + i];
        }
        __syncthreads();
        int warp = tid >> 5, lane = tid & 31;
        for (int g = warp; g < NG; g += 8) {
            unsigned masks[8];
            int total = 0;
            #pragma unroll
            for (int s = 0; s < 8; s++) {
                float v = gt[s * 32 + lane][g];
                masks[s] = __ballot_sync(0xffffffffu, v > 0.f);
                total += __popc(masks[s]);
            }
            int base = 0;
            if (lane == 0) base = atomicAdd(&counts[g], total);
            base = __shfl_sync(0xffffffffu, base, 0);
            int run = 0;
            #pragma unroll
            for (int s = 0; s < 8; s++) {
                unsigned m = masks[s];
                if (m & (1u << lane)) {
                    int slot = base + run + __popc(m & ((1u << lane) - 1u));
                    idxArr[(size_t)g * BATCH + slot] = b0 + s * 32 + lane;
                    ps[s * 32 + lane][g] = slot;
                }
                run += __popc(m);
            }
        }
        __syncthreads();
        for (int i = tid; i < 256 * NG; i += 256) {
            pos[(size_t)b0 * NG + i] = ps[i / NG][i % NG];
        }
        return;
    }
    if (bz >= PREP_TILES + PREP_CAST) {
        // ---- Wa pad region ----
        int kb = (bz - PREP_TILES - PREP_CAST) * 32;
        for (int e = tid; e < 32 * 32; e += 256) {
            int k = kb + (e >> 5), n = e & 31;
            float v = (n < NG) ? Wa[(size_t)k * NG + n] : 0.f;
            Wah[(size_t)n * DIM + k] = __float2half_rn(v);
        }
        return;
    }
    if (bz >= PREP_TILES) {
        // ---- X cast region ----
        int local = bz - PREP_TILES;
        int n4 = BATCH * DIM / 4;
        for (int i = local * 256 + tid; i < n4; i += PREP_CAST * 256) {
            float4 v = ((const float4*)X)[i];
            __half2 h0 = __floats2half2_rn(v.x, v.y);
            __half2 h1 = __floats2half2_rn(v.z, v.w);
            uint2 p;
            p.x = *(uint32_t*)&h0;
            p.y = *(uint32_t*)&h1;
            ((uint2*)Xh)[i] = p;
        }
        return;
    }

    // ---- weight transpose+cast tiles ----
    const float* in;
    __half* out;
    int K, N, g, tt;
    if (bz < 2304)      { g = bz / 128;          tt = bz % 128; in = W1;   out = W1h;   K = DIM;  N = HID2; }
    else if (bz < 2880) { bz -= 2304; g = bz / 32; tt = bz % 32; in = W2;   out = W2h;   K = HID2; N = HID;  }
    else if (bz < 3168) { bz -= 2880; g = bz / 16; tt = bz % 16; in = W3;   out = W3h;   K = HID;  N = HID;  }
    else                { bz -= 3168; g = 0;       tt = bz;      in = Wagg; out = Waggh; K = DAGG; N = DIM;  }
    in  += (size_t)g * K * N;
    out += (size_t)g * K * N;
    int ntn = N / 32;
    int k0 = (tt / ntn) * 32;
    int n0 = (tt % ntn) * 32;
    int tx = tid & 31, ty = tid >> 5;
    #pragma unroll
    for (int i = 0; i < 4; i++) {
        int r = ty + i * 8;
        t[r][tx] = in[(size_t)(k0 + r) * N + n0 + tx];
    }
    __syncthreads();
    #pragma unroll
    for (int i = 0; i < 4; i++) {
        int r = ty + i * 8;
        out[(size_t)(n0 + r) * K + k0 + tx] = __float2half_rn(t[tx][r]);
    }
}

// ---------------------------------------------------------------------------
// Shared GEMM geometry
// ---------------------------------------------------------------------------
#define BM  128
#define BN  128
#define BKH 64
#define LDH 72
#define TSZ (128 * LDH)
#define NSTAGE 3
#define GEMM_SMEM_BYTES (2 * NSTAGE * TSZ * 2)

// attn smem layout (fits inside GEMM_SMEM_BYTES)
#define AT_LDH 72
#define AT_ASZ (128 * AT_LDH)
#define AT_BSZ (32 * AT_LDH)
#define AT_CT_OFF (2 * AT_ASZ + 2 * AT_BSZ)

// ---------------------------------------------------------------------------
// GEMM1 + attention fused launch:
//   blockIdx.z in [0, NG): H1c = relu(gather(Xh) @ W1[g]^T + b1[g]) -> fp16
//   blockIdx.z == NG (y==0 only): tensor-core attention -> w
// GEMM1: R14-proven 128x128 tile, 3-stage, gather-A with clamp.
// ---------------------------------------------------------------------------
__global__ __launch_bounds__(256, 2)
void gemm1_attn_kernel(const __half* __restrict__ Xh, const __half* __restrict__ W1h,
                       const float* __restrict__ b1, __half* __restrict__ H1,
                       const int* __restrict__ idxArr, const int* __restrict__ counts,
                       const __half* __restrict__ Wah, const float* __restrict__ ba,
                       const float* __restrict__ genre, float* __restrict__ w) {
    extern __shared__ __half smh[];
    int tid  = threadIdx.x;
    int lane = tid & 31, warp = tid >> 5;

    if (blockIdx.z == NG) {
        // ================= attention slice =================
        if (blockIdx.y != 0) return;
        __half* As = smh;
        __half* Bs = smh + 2 * AT_ASZ;
        float*  Ct = (float*)(smh + AT_CT_OFF);
        uint32_t as_u = smem_u32(As);
        uint32_t bs_u = smem_u32(Bs);

        int m0 = blockIdx.x * 128;

        float acc[4][4];
        #pragma unroll
        for (int i = 0; i < 4; i++)
            #pragma unroll
            for (int r = 0; r < 4; r++) acc[i][r] = 0.f;

        int lr = tid >> 3, lc = (tid & 7) * 8;

        int lane8 = lane & 7;
        uint32_t a_off = (uint32_t)(((16 * warp + lane8 + ((lane >> 3) & 1) * 8) * AT_LDH
                                     + (lane >> 4) * 8) * 2);
        uint32_t b_off[2];
        #pragma unroll
        for (int p = 0; p < 2; p++)
            b_off[p] = (uint32_t)(((p * 16 + lane8 + (lane >> 4) * 8) * AT_LDH
                                   + ((lane >> 3) & 1) * 8) * 2);

        auto stage = [&](int bsel, int k0) {
            uint32_t abase = as_u + (uint32_t)(bsel * AT_ASZ) * 2;
            #pragma unroll
            for (int rr = 0; rr < 4; rr++) {
                int r = lr + rr * 32;
                cp_async16(abase + (uint32_t)(r * AT_LDH + lc) * 2,
                           Xh + (size_t)(m0 + r) * DIM + k0 + lc);
            }
            uint32_t bbase = bs_u + (uint32_t)(bsel * AT_BSZ) * 2;
            int n = tid >> 3;
            cp_async16(bbase + (uint32_t)(n * AT_LDH + lc) * 2,
                       Wah + (size_t)n * DIM + k0 + lc);
        };

        stage(0, 0);
        CP_COMMIT();
        for (int c = 0; c < 8; c++) {
            int cur = c & 1;
            if (c < 7) {
                stage(cur ^ 1, (c + 1) * 64);
                CP_COMMIT();
                CP_WAIT(1);
            } else {
                CP_WAIT(0);
            }
            __syncthreads();
            uint32_t ab = as_u + (uint32_t)(cur * AT_ASZ) * 2;
            uint32_t bb = bs_u + (uint32_t)(cur * AT_BSZ) * 2;
            #pragma unroll
            for (int kk = 0; kk < 4; kk++) {
                uint32_t kb = (uint32_t)(kk * 16 * 2);
                uint32_t af[4], bf[2][4];
                ldsm_x4(ab + a_off + kb, af);
                ldsm_x4(bb + b_off[0] + kb, bf[0]);
                ldsm_x4(bb + b_off[1] + kb, bf[1]);
                mma16(acc[0], af, &bf[0][0]);
                mma16(acc[1], af, &bf[0][2]);
                mma16(acc[2], af, &bf[1][0]);
                mma16(acc[3], af, &bf[1][2]);
            }
            __syncthreads();
        }

        #pragma unroll
        for (int wn = 0; wn < 4; wn++) {
            int c0 = wn * 8 + 2 * (lane & 3);
            int r0 = 16 * warp + (lane >> 2);
            Ct[r0 * 33 + c0]       = acc[wn][0];
            Ct[r0 * 33 + c0 + 1]   = acc[wn][1];
            Ct[(r0 + 8) * 33 + c0]     = acc[wn][2];
            Ct[(r0 + 8) * 33 + c0 + 1] = acc[wn][3];
        }
        __syncthreads();

        if (tid < 128) {
            int b = m0 + tid;
            float l[NG];
            float mx = -1e30f;
            #pragma unroll
            for (int g = 0; g < NG; g++) {
                l[g] = Ct[tid * 33 + g] + ba[g];
                mx = fmaxf(mx, l[g]);
            }
            float s = 0.f;
            #pragma unroll
            for (int g = 0; g < NG; g++) {
                l[g] = expf(l[g] - mx);
                s += l[g];
            }
            float inv = 1.f / s;
            #pragma unroll
            for (int g = 0; g < NG; g++) {
                float gv = genre[(size_t)b * NG + g];
                w[(size_t)b * NG + g] = (gv > 0.f) ? l[g] * inv * gv : 0.f;
            }
        }
        return;
    }

    // ================= GEMM1 slice (R14-proven path) =================
    int g = blockIdx.z;
    int m0 = blockIdx.x * BM;
    int cnt = counts[g];
    if (m0 >= cnt) return;
    const __half* W = W1h + (size_t)g * HID2 * DIM;
    const float* bias = b1 + (size_t)g * HID2;
    const int* gidx = idxArr + (size_t)g * BATCH;
    __half* C = H1 + (size_t)g * BATCH * HID2;

    __half* As = smh;
    __half* Bs = smh + NSTAGE * TSZ;
    uint32_t as_u = smem_u32(As);
    uint32_t bs_u = smem_u32(Bs);

    int n0 = blockIdx.y * BN;
    int wm_base = (warp >> 1) * 32;
    int wn_base = (warp & 1) * 64;

    float acc[2][8][4];
    #pragma unroll
    for (int i = 0; i < 2; i++)
        #pragma unroll
        for (int j = 0; j < 8; j++)
            #pragma unroll
            for (int r = 0; r < 4; r++) acc[i][j][r] = 0.f;

    int lr = tid >> 3, lc = (tid & 7) * 8;

    const __half* arow_ptr[4];
    #pragma unroll
    for (int rr = 0; rr < 4; rr++) {
        int grow = m0 + lr + rr * 32;
        int cl = (grow < cnt) ? grow : (cnt - 1);   // padded rows never consumed
        arow_ptr[rr] = Xh + (size_t)gidx[cl] * DIM;
    }

    int lane8 = lane & 7;
    uint32_t a_off[2];
    #pragma unroll
    for (int wm = 0; wm < 2; wm++) {
        int row = wm_base + wm * 16 + lane8 + ((lane >> 3) & 1) * 8;
        int kof = (lane >> 4) * 8;
        a_off[wm] = (uint32_t)((row * LDH + kof) * 2);
    }
    uint32_t b_off[4];
    #pragma unroll
    for (int wnp = 0; wnp < 4; wnp++) {
        int row = wn_base + wnp * 16 + lane8 + (lane >> 4) * 8;
        int kof = ((lane >> 3) & 1) * 8;
        b_off[wnp] = (uint32_t)((row * LDH + kof) * 2);
    }

    const int nchunks = DIM / BKH;   // 8

    auto stage = [&](int bsel, int k0) {
        uint32_t abase = as_u + (uint32_t)(bsel * TSZ) * 2;
        #pragma unroll
        for (int rr = 0; rr < 4; rr++) {
            int r = lr + rr * 32;
            cp_async16(abase + (uint32_t)(r * LDH + lc) * 2, arow_ptr[rr] + k0 + lc);
        }
        uint32_t bbase = bs_u + (uint32_t)(bsel * TSZ) * 2;
        #pragma unroll
        for (int rr = 0; rr < 4; rr++) {
            int n = lr + rr * 32;
            cp_async16(bbase + (uint32_t)(n * LDH + lc) * 2,
                       W + (size_t)(n0 + n) * DIM + k0 + lc);
        }
    };

    stage(0, 0);
    CP_COMMIT();
    stage(1, BKH);
    CP_COMMIT();

    for (int c = 0; c < nchunks; c++) {
        if (c + 1 < nchunks) { CP_WAIT(1); } else { CP_WAIT(0); }
        __syncthreads();
        if (c + 2 < nchunks) {
            stage((c + 2) % NSTAGE, (c + 2) * BKH);
            CP_COMMIT();
        }
        int cur = c % NSTAGE;
        uint32_t ab = as_u + (uint32_t)(cur * TSZ) * 2;
        uint32_t bb = bs_u + (uint32_t)(cur * TSZ) * 2;

        #pragma unroll
        for (int kk = 0; kk < 4; kk++) {
            uint32_t kb = (uint32_t)(kk * 16 * 2);
            uint32_t af[2][4], bf[4][4];
            ldsm_x4(ab + a_off[0] + kb, af[0]);
            ldsm_x4(ab + a_off[1] + kb, af[1]);
            #pragma unroll
            for (int wnp = 0; wnp < 4; wnp++)
                ldsm_x4(bb + b_off[wnp] + kb, bf[wnp]);
            #pragma unroll
            for (int wm = 0; wm < 2; wm++)
                #pragma unroll
                for (int wnp = 0; wnp < 4; wnp++) {
                    mma16(acc[wm][2 * wnp],     af[wm], &bf[wnp][0]);
                    mma16(acc[wm][2 * wnp + 1], af[wm], &bf[wnp][2]);
                }
        }
    }

    #pragma unroll
    for (int wm = 0; wm < 2; wm++) {
        int r0 = m0 + wm_base + wm * 16 + (lane >> 2);
        #pragma unroll
        for (int wn = 0; wn < 8; wn++) {
            int c0 = n0 + wn_base + wn * 8 + 2 * (lane & 3);
            float b0 = bias[c0], b1v = bias[c0 + 1];
            float v0 = fmaxf(acc[wm][wn][0] + b0, 0.f);
            float v1 = fmaxf(acc[wm][wn][1] + b1v, 0.f);
            float v2 = fmaxf(acc[wm][wn][2] + b0, 0.f);
            float v3 = fmaxf(acc[wm][wn][3] + b1v, 0.f);
            *(__half2*)(C + (size_t)r0 * HID2 + c0)       = __floats2half2_rn(v0, v1);
            *(__half2*)(C + (size_t)(r0 + 8) * HID2 + c0) = __floats2half2_rn(v2, v3);
        }
    }
}

// ---------------------------------------------------------------------------
// fp16 GEMM template (agg GEMM: MODE 3 concat [Xh|Rh], fp32 out)
// ---------------------------------------------------------------------------
template<int ACT, int OUTH, int MODE>
__global__ __launch_bounds__(256, 2)
void gemm_fp16_kernel(const __half* __restrict__ A, const __half* __restrict__ Rp,
                      const __half* __restrict__ W, const float* __restrict__ bias,
                      void* __restrict__ Cv,
                      int N, int K, int lda,
                      long long sA, long long sW, long long sB, long long sC,
                      const int* __restrict__ idxArr, const int* __restrict__ counts) {
    int g = blockIdx.z;
    int m0 = blockIdx.x * BM;
    int cnt = 0;
    if (MODE == 1) {
        cnt = counts[g];
        if (m0 >= cnt) return;
    }
    A    += (size_t)g * sA;
    W    += (size_t)g * sW;
    bias += (size_t)g * sB;
    const int* gidx = idxArr + (size_t)g * BATCH;

    extern __shared__ __half smh[];
    __half* As = smh;
    __half* Bs = smh + NSTAGE * TSZ;
    uint32_t as_u = smem_u32(As);
    uint32_t bs_u = smem_u32(Bs);

    int tid  = threadIdx.x;
    int n0   = blockIdx.y * BN;
    int lane = tid & 31, warp = tid >> 5;
    int wm_base = (warp >> 1) * 32;
    int wn_base = (warp & 1) * 64;

    float acc[2][8][4];
    #pragma unroll
    for (int i = 0; i < 2; i++)
        #pragma unroll
        for (int j = 0; j < 8; j++)
            #pragma unroll
            for (int r = 0; r < 4; r++) acc[i][j][r] = 0.f;

    int lr = tid >> 3, lc = (tid & 7) * 8;

    const __half* arow_ptr[4];
    #pragma unroll
    for (int rr = 0; rr < 4; rr++) {
        int grow = m0 + lr + rr * 32;
        if (MODE == 1) {
            int cl = (grow < cnt) ? grow : (cnt - 1);
            arow_ptr[rr] = A + (size_t)gidx[cl] * lda;
        } else {
            arow_ptr[rr] = A + (size_t)grow * lda;
        }
    }

    int lane8 = lane & 7;
    uint32_t a_off[2];
    #pragma unroll
    for (int wm = 0; wm < 2; wm++) {
        int row = wm_base + wm * 16 + lane8 + ((lane >> 3) & 1) * 8;
        int kof = (lane >> 4) * 8;
        a_off[wm] = (uint32_t)((row * LDH + kof) * 2);
    }
    uint32_t b_off[4];
    #pragma unroll
    for (int wnp = 0; wnp < 4; wnp++) {
        int row = wn_base + wnp * 16 + lane8 + (lane >> 4) * 8;
        int kof = ((lane >> 3) & 1) * 8;
        b_off[wnp] = (uint32_t)((row * LDH + kof) * 2);
    }

    int nchunks = K / BKH;

    auto stage = [&](int bsel, int k0) {
        uint32_t abase = as_u + (uint32_t)(bsel * TSZ) * 2;
        #pragma unroll
        for (int rr = 0; rr < 4; rr++) {
            int r = lr + rr * 32;
            int gcol = k0 + lc;
            const __half* src;
            if (MODE == 3) {
                int grow = m0 + r;
                src = (gcol < DIM) ? (A + (size_t)grow * DIM + gcol)
                                   : (Rp + (size_t)grow * HID + (gcol - DIM));
            } else {
                src = arow_ptr[rr] + gcol;
            }
            cp_async16(abase + (uint32_t)(r * LDH + lc) * 2, src);
        }
        uint32_t bbase = bs_u + (uint32_t)(bsel * TSZ) * 2;
        #pragma unroll
        for (int rr = 0; rr < 4; rr++) {
            int n = lr + rr * 32;
            cp_async16(bbase + (uint32_t)(n * LDH + lc) * 2,
                       W + (size_t)(n0 + n) * K + k0 + lc);
        }
    };

    stage(0, 0);
    CP_COMMIT();
    if (nchunks > 1) {
        stage(1, BKH);
        CP_COMMIT();
    }

    for (int c = 0; c < nchunks; c++) {
        if (c + 1 < nchunks) { CP_WAIT(1); } else { CP_WAIT(0); }
        __syncthreads();
        if (c + 2 < nchunks) {
            stage((c + 2) % NSTAGE, (c + 2) * BKH);
            CP_COMMIT();
        }
        int cur = c % NSTAGE;
        uint32_t ab = as_u + (uint32_t)(cur * TSZ) * 2;
        uint32_t bb = bs_u + (uint32_t)(cur * TSZ) * 2;

        #pragma unroll
        for (int kk = 0; kk < 4; kk++) {
            uint32_t kb = (uint32_t)(kk * 16 * 2);
            uint32_t af[2][4], bf[4][4];
            ldsm_x4(ab + a_off[0] + kb, af[0]);
            ldsm_x4(ab + a_off[1] + kb, af[1]);
            #pragma unroll
            for (int wnp = 0; wnp < 4; wnp++)
                ldsm_x4(bb + b_off[wnp] + kb, bf[wnp]);
            #pragma unroll
            for (int wm = 0; wm < 2; wm++)
                #pragma unroll
                for (int wnp = 0; wnp < 4; wnp++) {
                    mma16(acc[wm][2 * wnp],     af[wm], &bf[wnp][0]);
                    mma16(acc[wm][2 * wnp + 1], af[wm], &bf[wnp][2]);
                }
        }
    }

    #pragma unroll
    for (int wm = 0; wm < 2; wm++) {
        int r0 = m0 + wm_base + wm * 16 + (lane >> 2);
        #pragma unroll
        for (int wn = 0; wn < 8; wn++) {
            int c0 = n0 + wn_base + wn * 8 + 2 * (lane & 3);
            float b0 = bias[c0], b1v = bias[c0 + 1];
            float v0 = acc[wm][wn][0] + b0;
            float v1 = acc[wm][wn][1] + b1v;
            float v2 = acc[wm][wn][2] + b0;
            float v3 = acc[wm][wn][3] + b1v;
            if (ACT) {
                v0 = fmaxf(v0, 0.f); v1 = fmaxf(v1, 0.f);
                v2 = fmaxf(v2, 0.f); v3 = fmaxf(v3, 0.f);
            }
            if (OUTH) {
                __half* C = (__half*)Cv + (size_t)g * sC;
                __half2 p0 = __floats2half2_rn(v0, v1);
                __half2 p1 = __floats2half2_rn(v2, v3);
                *(__half2*)(C + (size_t)r0 * N + c0)       = p0;
                *(__half2*)(C + (size_t)(r0 + 8) * N + c0) = p1;
            } else {
                float* C = (float*)Cv + (size_t)g * sC;
                *(float2*)(C + (size_t)r0 * N + c0)       = make_float2(v0, v1);
                *(float2*)(C + (size_t)(r0 + 8) * N + c0) = make_float2(v2, v3);
            }
        }
    }
}

// ---------------------------------------------------------------------------
// Fused GEMM2+GEMM3 (unchanged from R14; H3 fp16 out)
// ---------------------------------------------------------------------------
#define LDH2 136
#define H2TSZ (128 * LDH2)
#define G23_STAGE_BYTES (4 * TSZ * 2)
#define GEMM23_SMEM_BYTES (G23_STAGE_BYTES + H2TSZ * 2)

__global__ __launch_bounds__(256, 2)
void gemm23_fused_kernel(const __half* __restrict__ H1, const __half* __restrict__ W2,
                         const __half* __restrict__ W3,
                         const float* __restrict__ b2, const float* __restrict__ b3,
                         __half* __restrict__ H3,
                         const int* __restrict__ counts) {
    int g = blockIdx.z;
    int m0 = blockIdx.x * BM;
    if (m0 >= counts[g]) return;
    H1 += (size_t)g * BATCH * HID2;
    W2 += (size_t)g * HID * HID2;
    W3 += (size_t)g * HID * HID;
    b2 += (size_t)g * HID;
    b3 += (size_t)g * HID;
    H3 += (size_t)g * BATCH * HID;

    extern __shared__ __half smh[];
    __half* As  = smh;
    __half* Bs  = smh + 2 * TSZ;
    __half* H2s = smh + 4 * TSZ;
    uint32_t as_u  = smem_u32(As);
    uint32_t bs_u  = smem_u32(Bs);
    uint32_t h2_u  = smem_u32(H2s);

    int tid  = threadIdx.x;
    int lane = tid & 31, warp = tid >> 5;
    int wm_base = (warp >> 1) * 32;
    int wn_base = (warp & 1) * 64;

    float acc[2][8][4];
    #pragma unroll
    for (int i = 0; i < 2; i++)
        #pragma unroll
        for (int j = 0; j < 8; j++)
            #pragma unroll
            for (int r = 0; r < 4; r++) acc[i][j][r] = 0.f;

    int lr = tid >> 3, lc = (tid & 7) * 8;

    int lane8 = lane & 7;
    uint32_t a_off[2], a2_off[2];
    #pragma unroll
    for (int wm = 0; wm < 2; wm++) {
        int row = wm_base + wm * 16 + lane8 + ((lane >> 3) & 1) * 8;
        int kof = (lane >> 4) * 8;
        a_off[wm]  = (uint32_t)((row * LDH  + kof) * 2);
        a2_off[wm] = (uint32_t)((row * LDH2 + kof) * 2);
    }
    uint32_t b_off[4];
    #pragma unroll
    for (int wnp = 0; wnp < 4; wnp++) {
        int row = wn_base + wnp * 16 + lane8 + (lane >> 4) * 8;
        int kof = ((lane >> 3) & 1) * 8;
        b_off[wnp] = (uint32_t)((row * LDH + kof) * 2);
    }

    auto stage1 = [&](int bsel, int k0) {
        uint32_t abase = as_u + (uint32_t)(bsel * TSZ) * 2;
        #pragma unroll
        for (int rr = 0; rr < 4; rr++) {
            int r = lr + rr * 32;
            cp_async16(abase + (uint32_t)(r * LDH + lc) * 2,
                       H1 + (size_t)(m0 + r) * HID2 + k0 + lc);
        }
        uint32_t bbase = bs_u + (uint32_t)(bsel * TSZ) * 2;
        #pragma unroll
        for (int rr = 0; rr < 4; rr++) {
            int n = lr + rr * 32;
            cp_async16(bbase + (uint32_t)(n * LDH + lc) * 2,
                       W2 + (size_t)n * HID2 + k0 + lc);
        }
    };
    auto stage_w3 = [&](int bsel, int k0) {
        uint32_t bbase = bs_u + (uint32_t)(bsel * TSZ) * 2;
        #pragma unroll
        for (int rr = 0; rr < 4; rr++) {
            int n = lr + rr * 32;
            cp_async16(bbase + (uint32_t)(n * LDH + lc) * 2,
                       W3 + (size_t)n * HID + k0 + lc);
        }
    };

    auto mma_block = [&](uint32_t ab, uint32_t bb, const uint32_t* aoff) {
        #pragma unroll
        for (int kk = 0; kk < 4; kk++) {
            uint32_t kb = (uint32_t)(kk * 16 * 2);
            uint32_t af[2][4], bf[4][4];
            ldsm_x4(ab + aoff[0] + kb, af[0]);
            ldsm_x4(ab + aoff[1] + kb, af[1]);
            #pragma unroll
            for (int wnp = 0; wnp < 4; wnp++)
                ldsm_x4(bb + b_off[wnp] + kb, bf[wnp]);
            #pragma unroll
            for (int wm = 0; wm < 2; wm++)
                #pragma unroll
                for (int wnp = 0; wnp < 4; wnp++) {
                    mma16(acc[wm][2 * wnp],     af[wm], &bf[wnp][0]);
                    mma16(acc[wm][2 * wnp + 1], af[wm], &bf[wnp][2]);
                }
        }
    };

    stage1(0, 0);
    CP_COMMIT();
    for (int c = 0; c < 4; c++) {
        int cur = c & 1;
        if (c < 3) {
            stage1(cur ^ 1, (c + 1) * BKH);
            CP_COMMIT();
            CP_WAIT(1);
        } else {
            stage_w3(0, 0);
            CP_COMMIT();
            CP_WAIT(1);
        }
        __syncthreads();
        mma_block(as_u + (uint32_t)(cur * TSZ) * 2, bs_u + (uint32_t)(cur * TSZ) * 2, a_off);
        __syncthreads();
    }

    #pragma unroll
    for (int wm = 0; wm < 2; wm++) {
        int r0 = wm_base + wm * 16 + (lane >> 2);
        #pragma unroll
        for (int wn = 0; wn < 8; wn++) {
            int c0 = wn_base + wn * 8 + 2 * (lane & 3);
            float b0 = b2[c0], b1v = b2[c0 + 1];
            float v0 = fmaxf(acc[wm][wn][0] + b0, 0.f);
            float v1 = fmaxf(acc[wm][wn][1] + b1v, 0.f);
            float v2 = fmaxf(acc[wm][wn][2] + b0, 0.f);
            float v3 = fmaxf(acc[wm][wn][3] + b1v, 0.f);
            *(__half2*)(H2s + r0 * LDH2 + c0)       = __floats2half2_rn(v0, v1);
            *(__half2*)(H2s + (r0 + 8) * LDH2 + c0) = __floats2half2_rn(v2, v3);
            acc[wm][wn][0] = 0.f; acc[wm][wn][1] = 0.f;
            acc[wm][wn][2] = 0.f; acc[wm][wn][3] = 0.f;
        }
    }
    stage_w3(1, BKH);
    CP_COMMIT();
    CP_WAIT(0);
    __syncthreads();

    #pragma unroll
    for (int c2 = 0; c2 < 2; c2++) {
        uint32_t ab = h2_u + (uint32_t)(c2 * BKH) * 2;
        uint32_t bb = bs_u + (uint32_t)(c2 * TSZ) * 2;
        mma_block(ab, bb, a2_off);
    }

    #pragma unroll
    for (int wm = 0; wm < 2; wm++) {
        int r0 = wm_base + wm * 16 + (lane >> 2);
        #pragma unroll
        for (int wn = 0; wn < 8; wn++) {
            int c0 = wn_base + wn * 8 + 2 * (lane & 3);
            float b0 = b3[c0], b1v = b3[c0 + 1];
            float v0 = acc[wm][wn][0] + b0;
            float v1 = acc[wm][wn][1] + b1v;
            float v2 = acc[wm][wn][2] + b0;
            float v3 = acc[wm][wn][3] + b1v;
            *(__half2*)(H3 + (size_t)(m0 + r0) * HID + c0)     = __floats2half2_rn(v0, v1);
            *(__half2*)(H3 + (size_t)(m0 + r0 + 8) * HID + c0) = __floats2half2_rn(v2, v3);
        }
    }
}

// ---------------------------------------------------------------------------
// Weighted reduce (compacted, fp16 H3)
// ---------------------------------------------------------------------------
__global__ __launch_bounds__(256)
void reduce_kernel(const __half* __restrict__ H3, const float* __restrict__ w,
                   const int* __restrict__ pos, __half* __restrict__ Rh) {
    int idx = blockIdx.x * blockDim.x + threadIdx.x;
    int b = idx >> 5;
    int off = idx & 31;
    float r0 = 0.f, r1 = 0.f, r2 = 0.f, r3 = 0.f;
    const uint2* H = (const uint2*)H3;
    #pragma unroll
    for (int g = 0; g < NG; g++) {
        float wv = w[(size_t)b * NG + g];
        if (wv != 0.f) {
            int slot = pos[(size_t)b * NG + g];
            uint2 h = H[((size_t)g * BATCH + slot) * 32 + off];
            float2 f0 = __half22float2(*(__half2*)&h.x);
            float2 f1 = __half22float2(*(__half2*)&h.y);
            r0 += wv * f0.x; r1 += wv * f0.y;
            r2 += wv * f1.x; r3 += wv * f1.y;
        }
    }
    __half2 p0 = __floats2half2_rn(r0, r1);
    __half2 p1 = __floats2half2_rn(r2, r3);
    uint2 p;
    p.x = *(uint32_t*)&p0;
    p.y = *(uint32_t*)&p1;
    ((uint2*)Rh)[idx] = p;
}

// ---------------------------------------------------------------------------
// Launch
// ---------------------------------------------------------------------------
extern "C" void kernel_launch(void* const* d_in, const int* in_sizes, int n_in,
                              void* d_out, int out_size) {
    (void)in_sizes; (void)n_in; (void)out_size;
    const float* X     = (const float*)d_in[0];
    const float* genre = (const float*)d_in[1];
    const float* W1    = (const float*)d_in[2];
    const float* b1    = (const float*)d_in[3];
    const float* W2    = (const float*)d_in[4];
    const float* b2    = (const float*)d_in[5];
    const float* W3    = (const float*)d_in[6];
    const float* b3    = (const float*)d_in[7];
    const float* Wa    = (const float*)d_in[8];
    const float* ba    = (const float*)d_in[9];
    const float* Wagg  = (const float*)d_in[10];
    const float* bagg  = (const float*)d_in[11];
    float* out = (float*)d_out;

    float *w;
    __half *Xh, *W1h, *W2h, *W3h, *Waggh, *Wah, *H1h, *H3h, *Rh;
    int *counts, *idxArr, *pos;
    cudaGetSymbolAddress((void**)&w,      g_w);
    cudaGetSymbolAddress((void**)&Xh,     g_Xh);
    cudaGetSymbolAddress((void**)&W1h,    g_W1h);
    cudaGetSymbolAddress((void**)&W2h,    g_W2h);
    cudaGetSymbolAddress((void**)&W3h,    g_W3h);
    cudaGetSymbolAddress((void**)&Waggh,  g_Waggh);
    cudaGetSymbolAddress((void**)&Wah,    g_Wah);
    cudaGetSymbolAddress((void**)&H1h,    g_H1h);
    cudaGetSymbolAddress((void**)&H3h,    g_H3h);
    cudaGetSymbolAddress((void**)&Rh,     g_Rh);
    cudaGetSymbolAddress((void**)&counts, g_counts);
    cudaGetSymbolAddress((void**)&idxArr, g_idx);
    cudaGetSymbolAddress((void**)&pos,    g_pos);

    // Unconditional (idempotent, host-side, not captured) — no static guards.
    cudaFuncSetAttribute(gemm1_attn_kernel,
                         cudaFuncAttributeMaxDynamicSharedMemorySize, GEMM_SMEM_BYTES);
    cudaFuncSetAttribute(gemm_fp16_kernel<1, 0, 3>,
                         cudaFuncAttributeMaxDynamicSharedMemorySize, GEMM_SMEM_BYTES);
    cudaFuncSetAttribute(gemm23_fused_kernel,
                         cudaFuncAttributeMaxDynamicSharedMemorySize, GEMM23_SMEM_BYTES);

    // 0) counts zero (memset node) + fused prep/compact
    cudaMemsetAsync(counts, 0, 32 * sizeof(int));
    prep_compact_kernel<<<PREP_GRID, 256>>>(W1, W2, W3, Wagg, X, Wa, genre,
                                            W1h, W2h, W3h, Waggh, Xh, Wah,
                                            counts, idxArr, pos);

    // 1+2) GEMM1 (z<NG) + attention (z==NG) in one launch
    gemm1_attn_kernel<<<dim3(BATCH / BM, HID2 / BN, NG + 1), 256, GEMM_SMEM_BYTES>>>(
        Xh, W1h, b1, H1h, idxArr, counts, Wah, ba, genre, w);

    // 3+4) fused: H3c = (relu(H1c @ W2^T + b2)) @ W3^T + b3 -> fp16
    gemm23_fused_kernel<<<dim3(BATCH / BM, 1, NG), 256, GEMM23_SMEM_BYTES>>>(
        H1h, W2h, W3h, b2, b3, H3h, counts);

    // 5) Rh = fp16( sum_g w .* H3c[pos] )
    reduce_kernel<<<(BATCH * 32) / 256, 256>>>(H3h, w, pos, Rh);

    // 6) out = relu([Xh, Rh] @ Wagg^T + bagg) -> fp32
    gemm_fp16_kernel<1, 0, 3><<<dim3(BATCH / BM, DIM / BN, 1), 256, GEMM_SMEM_BYTES>>>(
        Xh, Rh, Waggh, bagg, out,
        DIM, DAGG, DAGG,
        0LL, 0LL, 0LL, 0LL,
        idxArr, counts);
}